// round 15
// baseline (speedup 1.0000x reference)
#include <cuda_runtime.h>
#include <cuda_bf16.h>
#include <cuda_fp16.h>
#include <cstdint>

// SimpleGraphSAGE on GB300 (sm_103a harness; baseline-PTX only — no tcgen05).
// Identity: mean_nbr(x) @ W_bot == mean_nbr(x @ W_bot).
// Per layer: Yself[N,64](fp32) | Ynbr[N,64](fp16) = X[N,64] @ [W_top | W_bot]
//            h[i] = act(Yself[i] + b + (1/16) * sum_e Ynbr[src[16i+e]])
// Graph: dst = repeat(arange(N),16) -> node i's neighbors are src[16i..16i+15].

#define NN    100000
#define DEG   16
#define F     64
#define MTILE 128
#define NT    ((NN + MTILE - 1) / MTILE)   // 782 tiles
#define PGRID 296                           // persistent CTAs (2/SM)
#define GTHR  512                           // GEMM threads per CTA (16 warps)

// Static device scratch (no allocations allowed).
__device__ __align__(128) float  g_Yself[(size_t)NN * F];
__device__ __align__(128) __half g_Ynbr [(size_t)NN * F];
__device__ __align__(128) float  g_h    [(size_t)NN * F];
// Fragment-ready split weights: [layer][(ks*16+nt)*32 + lane] -> uint4{bh0,bh1,bl0,bl1}
__device__ __align__(128) uint4  g_Bf[2][2048];

#define MMA_BF16(c, a0, a1, a2, a3, b0, b1)                               \
    asm volatile(                                                          \
        "mma.sync.aligned.m16n8k16.row.col.f32.bf16.bf16.f32 "            \
        "{%0,%1,%2,%3}, {%4,%5,%6,%7}, {%8,%9}, {%0,%1,%2,%3};"           \
        : "+f"((c)[0]), "+f"((c)[1]), "+f"((c)[2]), "+f"((c)[3])          \
        : "r"(a0), "r"(a1), "r"(a2), "r"(a3), "r"(b0), "r"(b1))

__device__ __forceinline__ void split_pack(float x0, float x1,
                                           uint32_t& hi, uint32_t& lo) {
    __nv_bfloat162 h = __floats2bfloat162_rn(x0, x1);
    float r0 = x0 - __low2float(h), r1 = x1 - __high2float(h);
    __nv_bfloat162 l = __floats2bfloat162_rn(r0, r1);
    hi = *reinterpret_cast<uint32_t*>(&h);
    lo = *reinterpret_cast<uint32_t*>(&l);
}

__device__ __forceinline__ void cp_async16(uint32_t saddr, const void* g) {
    asm volatile("cp.async.ca.shared.global [%0], [%1], 16;" :: "r"(saddr), "l"(g));
}

// ---- One-shot: fragment-ready split weights for both layers ----
// Wcat[k][n] = n<64 ? W[k*64+n] : W[(64+k)*64+(n-64)] ; word kw = (k=2kw, 2kw+1)
// mma frag: lane l, step ks, tile nt: col = nt*8 + (l>>2); kw0 = ks*8+(l&3), kw1 = kw0+4.
__global__ void prep_w(const float* __restrict__ W1, const float* __restrict__ W2)
{
    const int id    = blockIdx.x * 256 + threadIdx.x;   // 4096 total
    const int layer = id >> 11;
    const int slot  = id & 2047;                         // (ks*16+nt)*32 + l
    const int l     = slot & 31;
    const int nt    = (slot >> 5) & 15;
    const int ks    = slot >> 9;
    const float* W  = layer ? W2 : W1;
    const int col   = nt * 8 + (l >> 2);
    uint32_t hiw[2], low[2];
    #pragma unroll
    for (int j = 0; j < 2; j++) {
        const int kw = ks * 8 + (l & 3) + j * 4;
        const int k0 = 2 * kw, k1 = k0 + 1;
        float x0, x1;
        if (col < 64) { x0 = W[k0 * 64 + col];               x1 = W[k1 * 64 + col]; }
        else          { x0 = W[(64 + k0) * 64 + (col - 64)]; x1 = W[(64 + k1) * 64 + (col - 64)]; }
        split_pack(x0, x1, hiw[j], low[j]);
    }
    g_Bf[layer][slot] = make_uint4(hiw[0], hiw[1], low[0], low[1]);
}

// ---- smem layout (u32 words) ----
// raw X ring: 2 buffers of 128 rows x 72 floats (RSTR=72 -> conflict-free
// A LDS.64 fragment pattern). B: uint4[2048] verbatim (LDS.128, clean).
#define RSTR   72
#define RAWW   (128 * RSTR)                 // 9216 words per buffer
#define OFF_B  (2 * RAWW)                   // 18432
#define SMEM_WORDS (OFF_B + 4096 * 2)       // 26624 words = 106496 B

// Persistent double-buffered GEMM, 512 threads: warp-group 0 (warps 0-7)
// computes n-tiles 0-7 -> Yself fp32; warp-group 1 (warps 8-15) computes
// n-tiles 8-15 -> Ynbr fp16. 32 accum regs/warp -> <=64 regs -> 32 warps/SM.
__global__ void __launch_bounds__(GTHR, 2) sage_gemm(
    const float* __restrict__ X, const uint4* __restrict__ Bf,
    float* __restrict__ Yself, __half* __restrict__ Ynbr)
{
    extern __shared__ uint32_t sm[];
    float* raw[2] = { (float*)sm, (float*)(sm + RAWW) };
    uint4* sB  = (uint4*)(sm + OFF_B);

    const int tid = threadIdx.x;

    // ---- copy helper: X tile -> raw[buf] via cp.async (2048 x 16B chunks) ----
    auto issue_copy = [&](int tile, int buf) {
        if (tile >= NT) return;
        const int base = tile * MTILE;
        uint32_t dst0 = (uint32_t)__cvta_generic_to_shared(raw[buf]);
        #pragma unroll
        for (int i = 0; i < 4; i++) {
            const int c    = tid + i * GTHR;       // chunk id 0..2047
            const int row  = c >> 4;               // 0..127
            const int part = c & 15;               // 16B chunk within row
            const int node = base + row;
            if (node < NN)
                cp_async16(dst0 + (uint32_t)(row * RSTR + part * 4) * 4,
                           X + (size_t)node * F + part * 4);
        }
    };

    // First prefetch in flight BEFORE the B copy so both overlap.
    int buf = 0;
    issue_copy(blockIdx.x, 0);
    asm volatile("cp.async.commit_group;");

    // ---- B to smem once per persistent CTA (overlaps cp.async flight) ----
    #pragma unroll
    for (int i = 0; i < 4; i++) {
        const int idx = tid + i * GTHR;
        sB[idx] = __ldg(&Bf[idx]);
    }

    const int warp = tid >> 5, l = tid & 31;
    const int wg   = warp >> 3;            // warp-group: 0 -> Yself, 1 -> Ynbr
    const int wr   = warp & 7;             // row-chunk owner within group
    const int lk   = l & 3;
    const int arow = wr * 16 + (l >> 2);

    for (int tile = blockIdx.x; tile < NT; tile += PGRID, buf ^= 1) {
        issue_copy(tile + PGRID, buf ^ 1);
        asm volatile("cp.async.commit_group;");
        asm volatile("cp.async.wait_group 1;");
        __syncthreads();     // raw[buf] (and, first iter, sB) ready

        const float* rA = raw[buf];
        const int base  = tile * MTILE;

        float c[8][4];
        #pragma unroll
        for (int j = 0; j < 8; j++) { c[j][0]=0.f; c[j][1]=0.f; c[j][2]=0.f; c[j][3]=0.f; }

        #pragma unroll
        for (int ks = 0; ks < 4; ks++) {
            const int kb = ks * 8;
            // A fragments: fp32 pairs from raw smem, split to bf16 hi/lo here.
            float2 f0 = *(const float2*)(rA +  arow      * RSTR + 2 * (kb + lk));
            float2 f1 = *(const float2*)(rA + (arow + 8) * RSTR + 2 * (kb + lk));
            float2 f2 = *(const float2*)(rA +  arow      * RSTR + 2 * (kb + lk + 4));
            float2 f3 = *(const float2*)(rA + (arow + 8) * RSTR + 2 * (kb + lk + 4));
            uint32_t ah0, ah1, ah2, ah3, al0, al1, al2, al3;
            split_pack(f0.x, f0.y, ah0, al0);
            split_pack(f1.x, f1.y, ah1, al1);
            split_pack(f2.x, f2.y, ah2, al2);
            split_pack(f3.x, f3.y, ah3, al3);

            #pragma unroll
            for (int j = 0; j < 8; j++) {
                uint4 b = sB[(ks * 16 + wg * 8 + j) * 32 + l];   // LDS.128, conflict-free
                MMA_BF16(c[j], ah0, ah1, ah2, ah3, b.x, b.y);
                MMA_BF16(c[j], ah0, ah1, ah2, ah3, b.z, b.w);
                MMA_BF16(c[j], al0, al1, al2, al3, b.x, b.y);
            }
        }

        // ---- Epilogue: wg0 -> Yself fp32, wg1 -> Ynbr fp16 ----
        const int r0 = base + arow;
        const int r1 = r0 + 8;
        if (wg == 0) {
            #pragma unroll
            for (int j = 0; j < 8; j++) {
                const int col = j * 8 + lk * 2;
                if (r0 < NN) *(float2*)(Yself + (size_t)r0 * F + col) = make_float2(c[j][0], c[j][1]);
                if (r1 < NN) *(float2*)(Yself + (size_t)r1 * F + col) = make_float2(c[j][2], c[j][3]);
            }
        } else {
            #pragma unroll
            for (int j = 0; j < 8; j++) {
                const int col = j * 8 + lk * 2;
                if (r0 < NN) *(__half2*)(Ynbr + (size_t)r0 * F + col) = __floats2half2_rn(c[j][0], c[j][1]);
                if (r1 < NN) *(__half2*)(Ynbr + (size_t)r1 * F + col) = __floats2half2_rn(c[j][2], c[j][3]);
            }
        }
        __syncthreads();     // all reads of raw[buf] done before next overwrite
    }
}

// out[i] = act( Yself[i] + b + (1/16) * sum_e Ynbr[src[16i+e]] )
// 8 threads per node (16B of fp16 each); half2 accumulation. Every gather
// LDG.128 covers full 128B lines.
__global__ void __launch_bounds__(256) sage_gather(
    const float* __restrict__ Yself, const __half* __restrict__ Ynbr,
    const float* __restrict__ bias, const int* __restrict__ src,
    float* __restrict__ out, int do_relu)
{
    const int tid  = threadIdx.x;
    const int lane = tid & 31;
    const int nq   = lane >> 3;          // node within warp quad (0..3)
    const int t8   = lane & 7;           // 16B chunk (8 fp16) within row
    const int node = (blockIdx.x * 256 + tid) >> 3;   // exact grid, no tail

    const int2 sp = *(const int2*)(src + (size_t)node * DEG + t8 * 2);

    __half2 hacc0 = __float2half2_rn(0.f), hacc1 = hacc0;
    __half2 hacc2 = hacc0, hacc3 = hacc0;

    #pragma unroll
    for (int e = 0; e < DEG; e++) {
        int s = __shfl_sync(0xffffffffu, (e & 1) ? sp.y : sp.x, (nq << 3) + (e >> 1));
        uint4 v = *(const uint4*)(Ynbr + (size_t)s * F + t8 * 8);
        hacc0 = __hadd2(hacc0, *(__half2*)&v.x);
        hacc1 = __hadd2(hacc1, *(__half2*)&v.y);
        hacc2 = __hadd2(hacc2, *(__half2*)&v.z);
        hacc3 = __hadd2(hacc3, *(__half2*)&v.w);
    }

    const float inv = 1.0f / (float)DEG;
    float2 m0 = __half22float2(hacc0);
    float2 m1 = __half22float2(hacc1);
    float2 m2 = __half22float2(hacc2);
    float2 m3 = __half22float2(hacc3);

    const float* selfp = Yself + (size_t)node * F + t8 * 8;
    float4 sa = *(const float4*)(selfp);
    float4 sb = *(const float4*)(selfp + 4);
    float4 ba = *(const float4*)(bias + t8 * 8);
    float4 bb = *(const float4*)(bias + t8 * 8 + 4);

    float r[8];
    r[0] = sa.x + ba.x + m0.x * inv;
    r[1] = sa.y + ba.y + m0.y * inv;
    r[2] = sa.z + ba.z + m1.x * inv;
    r[3] = sa.w + ba.w + m1.y * inv;
    r[4] = sb.x + bb.x + m2.x * inv;
    r[5] = sb.y + bb.y + m2.y * inv;
    r[6] = sb.z + bb.z + m3.x * inv;
    r[7] = sb.w + bb.w + m3.y * inv;
    if (do_relu) {
        #pragma unroll
        for (int j = 0; j < 8; j++) r[j] = fmaxf(r[j], 0.f);
    }
    float* op = out + (size_t)node * F + t8 * 8;
    *(float4*)(op)     = make_float4(r[0], r[1], r[2], r[3]);
    *(float4*)(op + 4) = make_float4(r[4], r[5], r[6], r[7]);
}

extern "C" void kernel_launch(void* const* d_in, const int* in_sizes, int n_in,
                              void* d_out, int out_size)
{
    const float* x   = (const float*)d_in[0];
    const float* W1  = (const float*)d_in[1];
    const float* b1  = (const float*)d_in[2];
    const float* W2  = (const float*)d_in[3];
    const float* b2  = (const float*)d_in[4];
    const int*   src = (const int*)  d_in[5];
    float* out = (float*)d_out;

    void* p = nullptr;
    cudaGetSymbolAddress(&p, g_Yself);  float*  Yself = (float*)p;
    cudaGetSymbolAddress(&p, g_Ynbr);   __half* Ynbr  = (__half*)p;
    cudaGetSymbolAddress(&p, g_h);      float*  h     = (float*)p;
    cudaGetSymbolAddress(&p, g_Bf);     uint4*  Bf    = (uint4*)p;

    const size_t smem = SMEM_WORDS * sizeof(uint32_t);  // 106496 B
    cudaFuncSetAttribute(sage_gemm, cudaFuncAttributeMaxDynamicSharedMemorySize, (int)smem);

    const int gather_grid = NN / 32;                     // 3125 (exact: 32 nodes/block)

    prep_w<<<16, 256>>>(W1, W2);
    sage_gemm  <<<PGRID, GTHR, smem>>>(x, Bf,        Yself, Ynbr);
    sage_gather<<<gather_grid, 256>>>(Yself, Ynbr, b1, src, h, 1);
    sage_gemm  <<<PGRID, GTHR, smem>>>(h, Bf + 2048, Yself, Ynbr);
    sage_gather<<<gather_grid, 256>>>(Yself, Ynbr, b2, src, out, 0);
}

// round 16
// speedup vs baseline: 1.1040x; 1.1040x over previous
#include <cuda_runtime.h>
#include <cuda_bf16.h>
#include <cuda_fp16.h>
#include <cstdint>

// SimpleGraphSAGE on GB300 (sm_103a harness; baseline-PTX only — no tcgen05).
// Identity: mean_nbr(x) @ W_bot == mean_nbr(x @ W_bot).
// Per layer: Yself[N,64](fp32) | Ynbr[N,64](fp16) = X[N,64] @ [W_top | W_bot]
//            h[i] = act(Yself[i] + b + (1/16) * sum_e Ynbr[src[16i+e]])
// Graph: dst = repeat(arange(N),16) -> node i's neighbors are src[16i..16i+15].

#define NN    100000
#define DEG   16
#define F     64
#define MTILE 128
#define NT    ((NN + MTILE - 1) / MTILE)   // 782 tiles
#define PGRID 296                           // persistent CTAs (2/SM)

// Static device scratch (no allocations allowed).
__device__ __align__(128) float  g_Yself[(size_t)NN * F];
__device__ __align__(128) __half g_Ynbr [(size_t)NN * F];
__device__ __align__(128) float  g_h    [(size_t)NN * F];
// Fragment-ready split weights: [layer][(ks*16+nt)*32 + lane] -> uint4{bh0,bh1,bl0,bl1}
__device__ __align__(128) uint4  g_Bf[2][2048];

#define MMA_BF16(c, a0, a1, a2, a3, b0, b1)                               \
    asm volatile(                                                          \
        "mma.sync.aligned.m16n8k16.row.col.f32.bf16.bf16.f32 "            \
        "{%0,%1,%2,%3}, {%4,%5,%6,%7}, {%8,%9}, {%0,%1,%2,%3};"           \
        : "+f"((c)[0]), "+f"((c)[1]), "+f"((c)[2]), "+f"((c)[3])          \
        : "r"(a0), "r"(a1), "r"(a2), "r"(a3), "r"(b0), "r"(b1))

__device__ __forceinline__ void split_pack(float x0, float x1,
                                           uint32_t& hi, uint32_t& lo) {
    __nv_bfloat162 h = __floats2bfloat162_rn(x0, x1);
    float r0 = x0 - __low2float(h), r1 = x1 - __high2float(h);
    __nv_bfloat162 l = __floats2bfloat162_rn(r0, r1);
    hi = *reinterpret_cast<uint32_t*>(&h);
    lo = *reinterpret_cast<uint32_t*>(&l);
}

// ---- One-shot: fragment-ready split weights for both layers ----
// Wcat[k][n] = n<64 ? W[k*64+n] : W[(64+k)*64+(n-64)] ; word kw = (k=2kw, 2kw+1)
// mma frag: lane l, step ks, tile nt: col = nt*8 + (l>>2); kw0 = ks*8+(l&3), kw1 = kw0+4.
__global__ void prep_w(const float* __restrict__ W1, const float* __restrict__ W2)
{
    const int id    = blockIdx.x * 256 + threadIdx.x;   // 4096 total
    const int layer = id >> 11;
    const int slot  = id & 2047;                         // (ks*16+nt)*32 + l
    const int l     = slot & 31;
    const int nt    = (slot >> 5) & 15;
    const int ks    = slot >> 9;
    const float* W  = layer ? W2 : W1;
    const int col   = nt * 8 + (l >> 2);
    uint32_t hiw[2], low[2];
    #pragma unroll
    for (int j = 0; j < 2; j++) {
        const int kw = ks * 8 + (l & 3) + j * 4;
        const int k0 = 2 * kw, k1 = k0 + 1;
        float x0, x1;
        if (col < 64) { x0 = W[k0 * 64 + col];               x1 = W[k1 * 64 + col]; }
        else          { x0 = W[(64 + k0) * 64 + (col - 64)]; x1 = W[(64 + k1) * 64 + (col - 64)]; }
        split_pack(x0, x1, hiw[j], low[j]);
    }
    g_Bf[layer][slot] = make_uint4(hiw[0], hiw[1], low[0], low[1]);
}

// Persistent barrier-free GEMM.
// - B (32 KB, fragment-ready) copied to static smem ONCE per CTA; single
//   __syncthreads; after that warps run fully independent through the tile
//   loop (each warp owns rows [16w,16w+16) of each tile; nothing shared).
// - A fragments loaded straight from global (LDG.64; lanes 0-3 = 32B
//   contiguous -> full sectors; each X row read exactly once per layer).
//   A goes through LSU/L1 while B goes through the smem crossbar: parallel.
__global__ void __launch_bounds__(256, 2) sage_gemm(
    const float* __restrict__ X, const uint4* __restrict__ Bf,
    float* __restrict__ Yself, __half* __restrict__ Ynbr)
{
    __shared__ uint4 sB[2048];   // 32 KB

    const int tid = threadIdx.x;
    #pragma unroll
    for (int i = 0; i < 8; i++) {
        const int idx = tid + i * 256;
        sB[idx] = __ldg(&Bf[idx]);
    }
    __syncthreads();   // the ONLY barrier

    const int warp = tid >> 5, l = tid & 31;
    const int lk   = l & 3;
    const int aoff = warp * 16 + (l >> 2);  // row within tile (first of pair)

    for (int tile = blockIdx.x; tile < NT; tile += PGRID) {
        const int base = tile * MTILE;
        const int r0   = base + aoff;
        const int r1   = r0 + 8;
        const bool v0  = r0 < NN;
        const bool v1  = r1 < NN;
        const float* x0p = X + (size_t)r0 * F;
        const float* x1p = X + (size_t)r1 * F;

        // ---- A: 16 LDG.64 issued upfront (MLP=16) ----
        float2 fA[4][4];   // [ks][0]=r0 klo, [1]=r1 klo, [2]=r0 khi, [3]=r1 khi
        #pragma unroll
        for (int ks = 0; ks < 4; ks++) {
            const int klo = 2 * (ks * 8 + lk);        // float offset
            const int khi = klo + 8;
            fA[ks][0] = v0 ? *(const float2*)(x0p + klo) : make_float2(0.f, 0.f);
            fA[ks][1] = v1 ? *(const float2*)(x1p + klo) : make_float2(0.f, 0.f);
            fA[ks][2] = v0 ? *(const float2*)(x0p + khi) : make_float2(0.f, 0.f);
            fA[ks][3] = v1 ? *(const float2*)(x1p + khi) : make_float2(0.f, 0.f);
        }

        float c[16][4];
        #pragma unroll
        for (int nt = 0; nt < 16; nt++) {
            c[nt][0] = 0.f; c[nt][1] = 0.f; c[nt][2] = 0.f; c[nt][3] = 0.f;
        }

        #pragma unroll
        for (int ks = 0; ks < 4; ks++) {
            uint32_t ah0, ah1, ah2, ah3, al0, al1, al2, al3;
            split_pack(fA[ks][0].x, fA[ks][0].y, ah0, al0);
            split_pack(fA[ks][1].x, fA[ks][1].y, ah1, al1);
            split_pack(fA[ks][2].x, fA[ks][2].y, ah2, al2);
            split_pack(fA[ks][3].x, fA[ks][3].y, ah3, al3);

            #pragma unroll
            for (int nt = 0; nt < 16; nt++) {
                uint4 b = sB[(ks * 16 + nt) * 32 + l];   // LDS.128, conflict-free
                MMA_BF16(c[nt], ah0, ah1, ah2, ah3, b.x, b.y);
                MMA_BF16(c[nt], ah0, ah1, ah2, ah3, b.z, b.w);
                MMA_BF16(c[nt], al0, al1, al2, al3, b.x, b.y);
            }
        }

        // ---- Epilogue: cols 0..63 -> Yself fp32, cols 64..127 -> Ynbr fp16 ----
        #pragma unroll
        for (int nt = 0; nt < 8; nt++) {
            const int col = nt * 8 + lk * 2;
            if (v0) *(float2*)(Yself + (size_t)r0 * F + col) = make_float2(c[nt][0], c[nt][1]);
            if (v1) *(float2*)(Yself + (size_t)r1 * F + col) = make_float2(c[nt][2], c[nt][3]);
        }
        #pragma unroll
        for (int nt = 8; nt < 16; nt++) {
            const int col = (nt - 8) * 8 + lk * 2;
            if (v0) *(__half2*)(Ynbr + (size_t)r0 * F + col) = __floats2half2_rn(c[nt][0], c[nt][1]);
            if (v1) *(__half2*)(Ynbr + (size_t)r1 * F + col) = __floats2half2_rn(c[nt][2], c[nt][3]);
        }
    }
}

// out[i] = act( Yself[i] + b + (1/16) * sum_e Ynbr[src[16i+e]] )
// 8 threads per node (16B of fp16 each); half2 accumulation. Every gather
// LDG.128 covers full 128B lines.
__global__ void __launch_bounds__(256) sage_gather(
    const float* __restrict__ Yself, const __half* __restrict__ Ynbr,
    const float* __restrict__ bias, const int* __restrict__ src,
    float* __restrict__ out, int do_relu)
{
    const int tid  = threadIdx.x;
    const int lane = tid & 31;
    const int nq   = lane >> 3;          // node within warp quad (0..3)
    const int t8   = lane & 7;           // 16B chunk (8 fp16) within row
    const int node = (blockIdx.x * 256 + tid) >> 3;   // exact grid, no tail

    const int2 sp = *(const int2*)(src + (size_t)node * DEG + t8 * 2);

    __half2 hacc0 = __float2half2_rn(0.f), hacc1 = hacc0;
    __half2 hacc2 = hacc0, hacc3 = hacc0;

    #pragma unroll
    for (int e = 0; e < DEG; e++) {
        int s = __shfl_sync(0xffffffffu, (e & 1) ? sp.y : sp.x, (nq << 3) + (e >> 1));
        uint4 v = *(const uint4*)(Ynbr + (size_t)s * F + t8 * 8);
        hacc0 = __hadd2(hacc0, *(__half2*)&v.x);
        hacc1 = __hadd2(hacc1, *(__half2*)&v.y);
        hacc2 = __hadd2(hacc2, *(__half2*)&v.z);
        hacc3 = __hadd2(hacc3, *(__half2*)&v.w);
    }

    const float inv = 1.0f / (float)DEG;
    float2 m0 = __half22float2(hacc0);
    float2 m1 = __half22float2(hacc1);
    float2 m2 = __half22float2(hacc2);
    float2 m3 = __half22float2(hacc3);

    const float* selfp = Yself + (size_t)node * F + t8 * 8;
    float4 sa = *(const float4*)(selfp);
    float4 sb = *(const float4*)(selfp + 4);
    float4 ba = *(const float4*)(bias + t8 * 8);
    float4 bb = *(const float4*)(bias + t8 * 8 + 4);

    float r[8];
    r[0] = sa.x + ba.x + m0.x * inv;
    r[1] = sa.y + ba.y + m0.y * inv;
    r[2] = sa.z + ba.z + m1.x * inv;
    r[3] = sa.w + ba.w + m1.y * inv;
    r[4] = sb.x + bb.x + m2.x * inv;
    r[5] = sb.y + bb.y + m2.y * inv;
    r[6] = sb.z + bb.z + m3.x * inv;
    r[7] = sb.w + bb.w + m3.y * inv;
    if (do_relu) {
        #pragma unroll
        for (int j = 0; j < 8; j++) r[j] = fmaxf(r[j], 0.f);
    }
    float* op = out + (size_t)node * F + t8 * 8;
    *(float4*)(op)     = make_float4(r[0], r[1], r[2], r[3]);
    *(float4*)(op + 4) = make_float4(r[4], r[5], r[6], r[7]);
}

extern "C" void kernel_launch(void* const* d_in, const int* in_sizes, int n_in,
                              void* d_out, int out_size)
{
    const float* x   = (const float*)d_in[0];
    const float* W1  = (const float*)d_in[1];
    const float* b1  = (const float*)d_in[2];
    const float* W2  = (const float*)d_in[3];
    const float* b2  = (const float*)d_in[4];
    const int*   src = (const int*)  d_in[5];
    float* out = (float*)d_out;

    void* p = nullptr;
    cudaGetSymbolAddress(&p, g_Yself);  float*  Yself = (float*)p;
    cudaGetSymbolAddress(&p, g_Ynbr);   __half* Ynbr  = (__half*)p;
    cudaGetSymbolAddress(&p, g_h);      float*  h     = (float*)p;
    cudaGetSymbolAddress(&p, g_Bf);     uint4*  Bf    = (uint4*)p;

    const int gather_grid = NN / 32;                     // 3125 (exact: 32 nodes/block)

    prep_w<<<16, 256>>>(W1, W2);
    sage_gemm  <<<PGRID, 256>>>(x, Bf,        Yself, Ynbr);
    sage_gather<<<gather_grid, 256>>>(Yself, Ynbr, b1, src, h, 1);
    sage_gemm  <<<PGRID, 256>>>(h, Bf + 2048, Yself, Ynbr);
    sage_gather<<<gather_grid, 256>>>(Yself, Ynbr, b2, src, out, 0);
}